// round 3
// baseline (speedup 1.0000x reference)
#include <cuda_runtime.h>
#include <math.h>

#define BATCH 2048
#define K 20
#define D 128
#define T 100
#define C 128
#define TK 40
#define HT 20
#define HC 512
#define PITCH 132   // token row pitch in floats (bank-conflict-free column access)

// smem float offsets
#define OFF_TOK   0
#define OFF_WT1   (TK*PITCH)            // 5280
#define OFF_WT2   (OFF_WT1 + 800)
#define OFF_TB1   (OFF_WT2 + 800)
#define OFF_TB2   (OFF_TB1 + 20)
#define OFF_TG    (OFF_TB2 + 40)
#define OFF_TB    (OFF_TG + 40)
#define OFF_CG    (OFF_TB + 40)
#define OFF_CB    (OFF_CG + 128)
#define OFF_CB1   (OFF_CB + 128)
#define OFF_CB2   (OFF_CB1 + 512)
#define OFF_EMB1  (OFF_CB2 + 128)
#define OFF_SCR   (OFF_EMB1 + 128)      // scratch: lnx(5280) + hact(10240) = 15520, or feat(9680)
#define SMEM_FLOATS (OFF_SCR + 15520)   // 23564 floats = 94256 bytes

struct P {
    const float* __restrict__ edge_table;
    const int*   __restrict__ src_eids;
    const int*   __restrict__ dst_eids;
    const int*   __restrict__ src2_e1;
    const int*   __restrict__ src2_e2;
    const int*   __restrict__ dst2_e1;
    const int*   __restrict__ dst2_e2;
    const float* __restrict__ dt_src;
    const float* __restrict__ dt_dst;
    const float* __restrict__ dt2_src;
    const float* __restrict__ dt2_dst;
    const float* __restrict__ pcc1;
    const float* __restrict__ pcc2;
    const float* __restrict__ time_w;
    const float* __restrict__ time_b;
    const float* __restrict__ proj_W;
    const float* __restrict__ proj_b;
    const float* __restrict__ eproj_W;
    const float* __restrict__ eproj_b;
    const float* __restrict__ tln_g;
    const float* __restrict__ tln_b;
    const float* __restrict__ tW1;
    const float* __restrict__ tb1;
    const float* __restrict__ tW2;
    const float* __restrict__ tb2;
    const float* __restrict__ cln_g;
    const float* __restrict__ cln_b;
    const float* __restrict__ cW1;
    const float* __restrict__ cb1;
    const float* __restrict__ cW2;
    const float* __restrict__ cb2;
    float* __restrict__ out;
};

__device__ __forceinline__ float gelu_f(float x) {
    return 0.5f * x * (1.0f + erff(x * 0.70710678118654752f));
}

__device__ __forceinline__ void run_mixer(int i, const P& p, float* sm, int tid) {
    float* tok  = sm + OFF_TOK;
    float* wt1  = sm + OFF_WT1;
    float* wt2  = sm + OFF_WT2;
    float* tb1s = sm + OFF_TB1;
    float* tb2s = sm + OFF_TB2;
    float* tgs  = sm + OFF_TG;
    float* tbs  = sm + OFF_TB;
    float* cgs  = sm + OFF_CG;
    float* cbs  = sm + OFF_CB;
    float* cb1s = sm + OFF_CB1;
    float* cb2s = sm + OFF_CB2;
    float* lnx  = sm + OFF_SCR;
    float* hact = sm + OFF_SCR + TK*PITCH;

    // ---- load this mixer's weights into smem ----
    for (int idx = tid; idx < 800; idx += 256) {
        wt1[idx] = p.tW1[i*800 + idx];
        wt2[idx] = p.tW2[i*800 + idx];
    }
    if (tid < HT) tb1s[tid] = p.tb1[i*HT + tid];
    if (tid < TK) {
        tb2s[tid] = p.tb2[i*TK + tid];
        tgs[tid]  = p.tln_g[i*TK + tid];
        tbs[tid]  = p.tln_b[i*TK + tid];
    }
    if (tid < C) {
        cgs[tid]  = p.cln_g[i*C + tid];
        cbs[tid]  = p.cln_b[i*C + tid];
        cb2s[tid] = p.cb2[i*C + tid];
    }
    for (int idx = tid; idx < HC; idx += 256) cb1s[idx] = p.cb1[i*HC + idx];
    __syncthreads();

    // ---- token mixing: LN over token axis + FFN (thread per channel) ----
    if (tid < C) {
        const int c = tid;
        float s = 0.f, ss = 0.f;
        #pragma unroll 8
        for (int t = 0; t < TK; t++) {
            float v = tok[t*PITCH + c];
            s += v; ss += v*v;
        }
        float m   = s * (1.0f/TK);
        float var = ss * (1.0f/TK) - m*m;
        float r   = rsqrtf(var + 1e-5f);
        #pragma unroll 8
        for (int t = 0; t < TK; t++)
            lnx[t*PITCH + c] = (tok[t*PITCH + c] - m) * r * tgs[t] + tbs[t];
        float a[HT];
        #pragma unroll
        for (int j = 0; j < HT; j++) a[j] = tb1s[j];
        for (int t = 0; t < TK; t++) {
            float v = lnx[t*PITCH + c];       // per-lane distinct
            #pragma unroll
            for (int j = 0; j < HT; j++) a[j] += v * wt1[t*HT + j];  // broadcast read
        }
        #pragma unroll
        for (int j = 0; j < HT; j++) a[j] = gelu_f(a[j]);
        for (int t = 0; t < TK; t++) {
            float d2 = tb2s[t];
            #pragma unroll
            for (int j = 0; j < HT; j++) d2 += a[j] * wt2[j*TK + t]; // broadcast read
            tok[t*PITCH + c] += d2;
        }
    }
    __syncthreads();

    // ---- channel LN (warp per token) ----
    {
        const int w = tid >> 5, lane = tid & 31;
        for (int t = w; t < TK; t += 8) {
            float v0 = tok[t*PITCH + lane];
            float v1 = tok[t*PITCH + lane + 32];
            float v2 = tok[t*PITCH + lane + 64];
            float v3 = tok[t*PITCH + lane + 96];
            float s  = v0 + v1 + v2 + v3;
            float ss = v0*v0 + v1*v1 + v2*v2 + v3*v3;
            #pragma unroll
            for (int o = 16; o > 0; o >>= 1) {
                s  += __shfl_xor_sync(0xffffffffu, s, o);
                ss += __shfl_xor_sync(0xffffffffu, ss, o);
            }
            float m = s * (1.0f/C);
            float r = rsqrtf(ss*(1.0f/C) - m*m + 1e-5f);
            lnx[t*PITCH + lane]      = (v0 - m)*r*cgs[lane]      + cbs[lane];
            lnx[t*PITCH + lane + 32] = (v1 - m)*r*cgs[lane + 32] + cbs[lane + 32];
            lnx[t*PITCH + lane + 64] = (v2 - m)*r*cgs[lane + 64] + cbs[lane + 64];
            lnx[t*PITCH + lane + 96] = (v3 - m)*r*cgs[lane + 96] + cbs[lane + 96];
        }
    }
    __syncthreads();

    // ---- channel FFN: [40,128] -> GELU([40,512]) -> [40,128], hidden in 2 chunks ----
    const int c   = tid & 127;
    const int grp = tid >> 7;
    const float* cW1p = p.cW1 + (size_t)i*C*HC;
    const float* cW2p = p.cW2 + (size_t)i*HC*C;
    float accB[20];
    #pragma unroll
    for (int tt = 0; tt < 20; tt++) accB[tt] = 0.f;

    for (int chunk = 0; chunk < 2; chunk++) {
        const int h = chunk*256 + tid;           // this thread's hidden unit
        const float bias = cb1s[h];
        // phase A: a1[t][h] over all 40 tokens, split into 2 halves of 20 for regs
        for (int th = 0; th < 2; th++) {
            float a[20];
            #pragma unroll
            for (int tt = 0; tt < 20; tt++) a[tt] = bias;
            for (int c4 = 0; c4 < 32; c4++) {
                float w0 = cW1p[(4*c4 + 0)*HC + h];   // coalesced across tid
                float w1 = cW1p[(4*c4 + 1)*HC + h];
                float w2 = cW1p[(4*c4 + 2)*HC + h];
                float w3 = cW1p[(4*c4 + 3)*HC + h];
                #pragma unroll
                for (int tt = 0; tt < 20; tt++) {
                    float4 v = *(const float4*)&lnx[(th*20 + tt)*PITCH + 4*c4];
                    float acc = a[tt];
                    acc = fmaf(v.x, w0, acc);
                    acc = fmaf(v.y, w1, acc);
                    acc = fmaf(v.z, w2, acc);
                    acc = fmaf(v.w, w3, acc);
                    a[tt] = acc;
                }
            }
            #pragma unroll
            for (int tt = 0; tt < 20; tt++)
                hact[(th*20 + tt)*256 + tid] = gelu_f(a[tt]);
        }
        __syncthreads();
        // phase B: out[t][c] += sum_h hact[t][h] * cW2[h][c]
        for (int h4 = 0; h4 < 64; h4++) {
            const int hh = chunk*256 + 4*h4;
            float w0 = cW2p[(hh + 0)*C + c];      // coalesced + broadcast across grp
            float w1 = cW2p[(hh + 1)*C + c];
            float w2 = cW2p[(hh + 2)*C + c];
            float w3 = cW2p[(hh + 3)*C + c];
            #pragma unroll
            for (int tt = 0; tt < 20; tt++) {
                float4 v = *(const float4*)&hact[(grp*20 + tt)*256 + 4*h4];
                float acc = accB[tt];
                acc = fmaf(v.x, w0, acc);
                acc = fmaf(v.y, w1, acc);
                acc = fmaf(v.z, w2, acc);
                acc = fmaf(v.w, w3, acc);
                accB[tt] = acc;
            }
        }
        __syncthreads();
    }
    #pragma unroll
    for (int tt = 0; tt < 20; tt++)
        tok[(grp*20 + tt)*PITCH + c] += accB[tt] + cb2s[c];
    __syncthreads();
}

__global__ __launch_bounds__(256, 2)
void repeat_mixer_kernel(P p) {
    const int b   = blockIdx.x;
    const int tid = threadIdx.x;
    extern __shared__ float sm[];
    float* tok  = sm + OFF_TOK;
    float* emb1 = sm + OFF_EMB1;
    float* feat = sm + OFF_SCR;

    __shared__ int   s_eid[3][K];
    __shared__ float s_dt[K];

    const int cg_ = tid & 127;
    const int grp = tid >> 7;

    // ================= one-hop branch: build tokens [40,128] =================
    for (int half = 0; half < 2; half++) {
        const int*   eidp = half ? p.dst_eids : p.src_eids;
        const float* dtp  = half ? p.dt_dst   : p.dt_src;
        if (tid < K) { s_eid[0][tid] = eidp[b*K + tid]; s_dt[tid] = dtp[b*K + tid]; }
        __syncthreads();
        for (int idx = tid; idx < K*228; idx += 256) {
            int t = idx / 228, j = idx - t*228;
            int eid = s_eid[0][t];
            float v;
            if (j < D) v = p.edge_table[(long long)eid*D + j];
            else {
                int jt = j - D;
                v = (eid == 0) ? 0.f : cosf(s_dt[t]*p.time_w[jt] + p.time_b[jt]);
            }
            feat[t*228 + j] = v;
        }
        __syncthreads();
        {
            float acc[10];
            float bias = p.proj_b[cg_];
            #pragma unroll
            for (int tt = 0; tt < 10; tt++) acc[tt] = bias;
            for (int j4 = 0; j4 < 57; j4++) {
                float w0 = p.proj_W[(4*j4 + 0)*C + cg_];
                float w1 = p.proj_W[(4*j4 + 1)*C + cg_];
                float w2 = p.proj_W[(4*j4 + 2)*C + cg_];
                float w3 = p.proj_W[(4*j4 + 3)*C + cg_];
                #pragma unroll
                for (int tt = 0; tt < 10; tt++) {
                    float4 f = *(const float4*)&feat[(grp*10 + tt)*228 + 4*j4];
                    float a = acc[tt];
                    a = fmaf(f.x, w0, a);
                    a = fmaf(f.y, w1, a);
                    a = fmaf(f.z, w2, a);
                    a = fmaf(f.w, w3, a);
                    acc[tt] = a;
                }
            }
            #pragma unroll
            for (int tt = 0; tt < 10; tt++)
                tok[(half*K + grp*10 + tt)*PITCH + cg_] = acc[tt];
        }
        __syncthreads();
    }

    // mixers 0,1
    run_mixer(0, p, sm, tid);
    run_mixer(1, p, sm, tid);

    // edge_emb = mean over tokens
    if (tid < C) {
        float s = 0.f;
        for (int t = 0; t < TK; t++) s += tok[t*PITCH + tid];
        emb1[tid] = s * (1.0f/TK);
    }
    __syncthreads();

    // ================= two-hop branch =================
    for (int half = 0; half < 2; half++) {
        const int*   e1p = half ? p.dst2_e1  : p.src2_e1;
        const int*   e2p = half ? p.dst2_e2  : p.src2_e2;
        const int*   e0p = half ? p.dst_eids : p.src_eids;
        const float* dtp = half ? p.dt2_dst  : p.dt2_src;
        if (tid < K) {
            s_eid[0][tid] = e1p[b*K + tid];
            s_eid[1][tid] = e2p[b*K + tid];
            s_eid[2][tid] = e0p[b*K + tid];
            s_dt[tid]     = dtp[b*K + tid];
        }
        __syncthreads();
        for (int idx = tid; idx < K*484; idx += 256) {
            int t = idx / 484, j = idx - t*484;
            float v;
            if (j < 3*D) {
                int eid = s_eid[j >> 7][t];
                v = p.edge_table[(long long)eid*D + (j & 127)];
            } else {
                int jt = j - 3*D;
                int e1 = s_eid[0][t];
                v = (e1 == 0) ? 0.f : cosf(s_dt[t]*p.time_w[jt] + p.time_b[jt]);
            }
            feat[t*484 + j] = v;
        }
        __syncthreads();
        {
            const float* eW = p.eproj_W + (size_t)half*484*C;
            float acc[10];
            float bias = p.eproj_b[half*C + cg_];
            #pragma unroll
            for (int tt = 0; tt < 10; tt++) acc[tt] = bias;
            for (int j4 = 0; j4 < 121; j4++) {
                float w0 = eW[(4*j4 + 0)*C + cg_];
                float w1 = eW[(4*j4 + 1)*C + cg_];
                float w2 = eW[(4*j4 + 2)*C + cg_];
                float w3 = eW[(4*j4 + 3)*C + cg_];
                #pragma unroll
                for (int tt = 0; tt < 10; tt++) {
                    float4 f = *(const float4*)&feat[(grp*10 + tt)*484 + 4*j4];
                    float a = acc[tt];
                    a = fmaf(f.x, w0, a);
                    a = fmaf(f.y, w1, a);
                    a = fmaf(f.z, w2, a);
                    a = fmaf(f.w, w3, a);
                    acc[tt] = a;
                }
            }
            #pragma unroll
            for (int tt = 0; tt < 10; tt++)
                tok[(half*K + grp*10 + tt)*PITCH + cg_] = acc[tt];
        }
        __syncthreads();
    }

    // mixers 2,3
    run_mixer(2, p, sm, tid);
    run_mixer(3, p, sm, tid);

    // high_emb mean + pcc-softmax combine
    if (tid < C) {
        float s = 0.f;
        for (int t = 0; t < TK; t++) s += tok[t*PITCH + tid];
        float e2v = s * (1.0f/TK);
        float a1 = p.pcc1[b], a2 = p.pcc2[b];
        float mx = fmaxf(a1, a2);
        float x1 = expf(a1 - mx), x2 = expf(a2 - mx);
        float w1 = x1 / (x1 + x2);
        p.out[b*C + tid] = w1*emb1[tid] + (1.0f - w1)*e2v;
    }
}

extern "C" void kernel_launch(void* const* d_in, const int* in_sizes, int n_in,
                              void* d_out, int out_size) {
    P p;
    p.edge_table = (const float*)d_in[0];
    p.src_eids   = (const int*)  d_in[1];
    p.dst_eids   = (const int*)  d_in[2];
    p.src2_e1    = (const int*)  d_in[3];
    p.src2_e2    = (const int*)  d_in[4];
    p.dst2_e1    = (const int*)  d_in[5];
    p.dst2_e2    = (const int*)  d_in[6];
    p.dt_src     = (const float*)d_in[7];
    p.dt_dst     = (const float*)d_in[8];
    p.dt2_src    = (const float*)d_in[9];
    p.dt2_dst    = (const float*)d_in[10];
    p.pcc1       = (const float*)d_in[11];
    p.pcc2       = (const float*)d_in[12];
    p.time_w     = (const float*)d_in[13];
    p.time_b     = (const float*)d_in[14];
    p.proj_W     = (const float*)d_in[15];
    p.proj_b     = (const float*)d_in[16];
    p.eproj_W    = (const float*)d_in[17];
    p.eproj_b    = (const float*)d_in[18];
    p.tln_g      = (const float*)d_in[19];
    p.tln_b      = (const float*)d_in[20];
    p.tW1        = (const float*)d_in[21];
    p.tb1        = (const float*)d_in[22];
    p.tW2        = (const float*)d_in[23];
    p.tb2        = (const float*)d_in[24];
    p.cln_g      = (const float*)d_in[25];
    p.cln_b      = (const float*)d_in[26];
    p.cW1        = (const float*)d_in[27];
    p.cb1        = (const float*)d_in[28];
    p.cW2        = (const float*)d_in[29];
    p.cb2        = (const float*)d_in[30];
    p.out        = (float*)d_out;

    const int smem_bytes = SMEM_FLOATS * (int)sizeof(float);
    cudaFuncSetAttribute(repeat_mixer_kernel,
                         cudaFuncAttributeMaxDynamicSharedMemorySize, smem_bytes);
    repeat_mixer_kernel<<<BATCH, 256, smem_bytes>>>(p);
}

// round 12
// speedup vs baseline: 1.3068x; 1.3068x over previous
#include <cuda_runtime.h>
#include <math.h>

typedef unsigned long long ull;

#define BATCH 2048
#define K 20
#define D 128
#define T 100
#define C 128
#define TK 40
#define HT 20
#define HC 512

#define TOKP 128      // tok [40][128]
#define LNP 44        // lnxT [128][44]  (rows 176B, 16B aligned)
#define HACTP 44      // hactT [256][44]
#define STAGEP 42     // reduction staging pitch
#define PITCH1 232    // one-hop feat row pitch (228 used)
#define PITCH2 488    // two-hop feat row pitch (484 used)

// smem float offsets
#define OFF_TOK   0                     // 5120
#define OFF_WT1   5120                  // 800
#define OFF_WT2   5920                  // 800
#define OFF_TB1   6720                  // 20
#define OFF_TB2   6740                  // 40
#define OFF_TG    6780                  // 40
#define OFF_TB    6820                  // 40
#define OFF_CG    6860                  // 128
#define OFF_CB    6988                  // 128
#define OFF_CB1   7116                  // 512
#define OFF_CB2   7628                  // 128
#define OFF_EMB1  7756                  // 128
#define OFF_UNION 7884                  // lnxT(5632)+hactT(11264)=16896 | feat(<=9760)
#define OFF_HACT  (OFF_UNION + 5632)
#define SMEM_FLOATS (OFF_UNION + 16896) // 24780 floats = 99120 B

struct P {
    const float* __restrict__ edge_table;
    const int*   __restrict__ src_eids;
    const int*   __restrict__ dst_eids;
    const int*   __restrict__ src2_e1;
    const int*   __restrict__ src2_e2;
    const int*   __restrict__ dst2_e1;
    const int*   __restrict__ dst2_e2;
    const float* __restrict__ dt_src;
    const float* __restrict__ dt_dst;
    const float* __restrict__ dt2_src;
    const float* __restrict__ dt2_dst;
    const float* __restrict__ pcc1;
    const float* __restrict__ pcc2;
    const float* __restrict__ time_w;
    const float* __restrict__ time_b;
    const float* __restrict__ proj_W;
    const float* __restrict__ proj_b;
    const float* __restrict__ eproj_W;
    const float* __restrict__ eproj_b;
    const float* __restrict__ tln_g;
    const float* __restrict__ tln_b;
    const float* __restrict__ tW1;
    const float* __restrict__ tb1;
    const float* __restrict__ tW2;
    const float* __restrict__ tb2;
    const float* __restrict__ cln_g;
    const float* __restrict__ cln_b;
    const float* __restrict__ cW1;
    const float* __restrict__ cb1;
    const float* __restrict__ cW2;
    const float* __restrict__ cb2;
    float* __restrict__ out;
};

__device__ __forceinline__ float gelu_f(float x) {
    return 0.5f * x * (1.0f + erff(x * 0.70710678118654752f));
}

// ---- packed fp32x2 helpers ----
__device__ __forceinline__ ull fma2(ull a, ull b, ull c) {
    ull d;
    asm("fma.rn.f32x2 %0, %1, %2, %3;" : "=l"(d) : "l"(a), "l"(b), "l"(c));
    return d;
}
__device__ __forceinline__ ull dup2(float x) {
    ull d;
    asm("mov.b64 %0, {%1, %1};" : "=l"(d) : "f"(x));
    return d;
}
__device__ __forceinline__ ull pack2(float lo, float hi) {
    ull d;
    asm("mov.b64 %0, {%1, %2};" : "=l"(d) : "f"(lo), "f"(hi));
    return d;
}
__device__ __forceinline__ void unpack2(ull a, float& x, float& y) {
    asm("mov.b64 {%0, %1}, %2;" : "=f"(x), "=f"(y) : "l"(a));
}

// projection: tok[half*K + t][c] = b[c] + sum_j feat[t][j] * W[j][c]
__device__ __forceinline__ void project(const float* __restrict__ W,
                                        const float* __restrict__ bvec,
                                        const float* feat, float* tok,
                                        int nj4, int pitchf, int half, int tid) {
    const int c = tid & 127, grp = tid >> 7;
    const float bias = bvec[c];
    ull acc2[10];
    #pragma unroll
    for (int q = 0; q < 10; q++) acc2[q] = 0ull;
    for (int j4 = 0; j4 < nj4; j4++) {
        float wa = W[(4*j4 + 0)*C + c];
        float wb = W[(4*j4 + 1)*C + c];
        float wc = W[(4*j4 + 2)*C + c];
        float wd = W[(4*j4 + 3)*C + c];
        ull wp01 = pack2(wa, wb), wp23 = pack2(wc, wd);
        #pragma unroll
        for (int q = 0; q < 10; q++) {
            ulonglong2 f = *(const ulonglong2*)&feat[(grp*10 + q)*pitchf + 4*j4];
            acc2[q] = fma2(f.x, wp01, acc2[q]);
            acc2[q] = fma2(f.y, wp23, acc2[q]);
        }
    }
    #pragma unroll
    for (int q = 0; q < 10; q++) {
        float x, y; unpack2(acc2[q], x, y);
        tok[(half*K + grp*10 + q)*TOKP + c] = x + y + bias;
    }
}

__device__ __forceinline__ void run_mixer(int i, const P& p, float* sm, int tid) {
    float* tok   = sm + OFF_TOK;
    float* wt1   = sm + OFF_WT1;
    float* wt2   = sm + OFF_WT2;
    float* tb1s  = sm + OFF_TB1;
    float* tb2s  = sm + OFF_TB2;
    float* tgs   = sm + OFF_TG;
    float* tbs   = sm + OFF_TB;
    float* cgs   = sm + OFF_CG;
    float* cbs   = sm + OFF_CB;
    float* cb1s  = sm + OFF_CB1;
    float* cb2s  = sm + OFF_CB2;
    float* lnxT  = sm + OFF_UNION;
    float* hactT = sm + OFF_HACT;
    float* stage = sm + OFF_HACT;   // reused after last phase B

    // ---- stage this mixer's small weights ----
    for (int idx = tid; idx < 800; idx += 256) {
        wt1[idx] = p.tW1[i*800 + idx];
        wt2[idx] = p.tW2[i*800 + idx];
    }
    if (tid < HT) tb1s[tid] = p.tb1[i*HT + tid];
    if (tid < TK) {
        tb2s[tid] = p.tb2[i*TK + tid];
        tgs[tid]  = p.tln_g[i*TK + tid];
        tbs[tid]  = p.tln_b[i*TK + tid];
    }
    if (tid < C) {
        cgs[tid]  = p.cln_g[i*C + tid];
        cbs[tid]  = p.cln_b[i*C + tid];
        cb2s[tid] = p.cb2[i*C + tid];
    }
    for (int idx = tid; idx < HC; idx += 256) cb1s[idx] = p.cb1[i*HC + idx];
    __syncthreads();

    // ---- token mixing: per-(b,c) LN over token axis + register-resident FFN ----
    if (tid < 128) {
        const int c = tid;
        float v[40]; float s = 0.f, ssum = 0.f;
        #pragma unroll
        for (int t = 0; t < 40; t++) { v[t] = tok[t*TOKP + c]; s += v[t]; ssum += v[t]*v[t]; }
        float m = s * (1.f/40.f);
        float r = rsqrtf(ssum * (1.f/40.f) - m*m + 1e-5f);
        #pragma unroll
        for (int t = 0; t < 40; t++) v[t] = (v[t] - m) * r * tgs[t] + tbs[t];
        // a[j] = tb1[j] + sum_t v[t]*tW1[t][j], packed over j pairs
        ull a2[10];
        #pragma unroll
        for (int q = 0; q < 10; q++) a2[q] = pack2(tb1s[2*q], tb1s[2*q+1]);
        #pragma unroll 4
        for (int t = 0; t < 40; t++) {
            ull lv = dup2(v[t]);
            const ulonglong2* wr = (const ulonglong2*)&wt1[t*HT];
            #pragma unroll
            for (int k = 0; k < 5; k++) {
                ulonglong2 u = wr[k];
                a2[2*k]   = fma2(lv, u.x, a2[2*k]);
                a2[2*k+1] = fma2(lv, u.y, a2[2*k+1]);
            }
        }
        float a[20];
        #pragma unroll
        for (int q = 0; q < 10; q++) {
            float x, y; unpack2(a2[q], x, y);
            a[2*q] = gelu_f(x); a[2*q+1] = gelu_f(y);
        }
        // d2[t] = tb2[t] + sum_j a[j]*tW2[j][t], packed over t pairs
        ull d2[20];
        #pragma unroll
        for (int q = 0; q < 20; q++) d2[q] = pack2(tb2s[2*q], tb2s[2*q+1]);
        #pragma unroll 2
        for (int j = 0; j < 20; j++) {
            ull aj = dup2(a[j]);
            const ulonglong2* wr = (const ulonglong2*)&wt2[j*TK];
            #pragma unroll
            for (int k = 0; k < 10; k++) {
                ulonglong2 u = wr[k];
                d2[2*k]   = fma2(aj, u.x, d2[2*k]);
                d2[2*k+1] = fma2(aj, u.y, d2[2*k+1]);
            }
        }
        #pragma unroll
        for (int q = 0; q < 20; q++) {
            float x, y; unpack2(d2[q], x, y);
            tok[(2*q)*TOKP + c]   += x;
            tok[(2*q+1)*TOKP + c] += y;
        }
    }
    __syncthreads();

    // ---- channel LN (warp per token) -> transposed lnxT[c][t] ----
    {
        const int w = tid >> 5, lane = tid & 31;
        for (int t = w; t < 40; t += 8) {
            float v0 = tok[t*TOKP + lane];
            float v1 = tok[t*TOKP + lane + 32];
            float v2 = tok[t*TOKP + lane + 64];
            float v3 = tok[t*TOKP + lane + 96];
            float s  = v0 + v1 + v2 + v3;
            float ss = v0*v0 + v1*v1 + v2*v2 + v3*v3;
            #pragma unroll
            for (int o = 16; o > 0; o >>= 1) {
                s  += __shfl_xor_sync(0xffffffffu, s, o);
                ss += __shfl_xor_sync(0xffffffffu, ss, o);
            }
            float m = s * (1.f/128.f);
            float r = rsqrtf(ss*(1.f/128.f) - m*m + 1e-5f);
            lnxT[(lane)*LNP + t]    = (v0 - m)*r*cgs[lane]    + cbs[lane];
            lnxT[(lane+32)*LNP + t] = (v1 - m)*r*cgs[lane+32] + cbs[lane+32];
            lnxT[(lane+64)*LNP + t] = (v2 - m)*r*cgs[lane+64] + cbs[lane+64];
            lnxT[(lane+96)*LNP + t] = (v3 - m)*r*cgs[lane+96] + cbs[lane+96];
        }
    }
    __syncthreads();

    // ---- channel FFN ----
    const int htop = tid & 127;        // phase A: h slot (covers h0 and h0+128)
    const int thA  = tid >> 7;         // phase A: token half
    const int c0   = tid & 63, c1 = c0 + 64;
    const int thB  = (tid >> 6) & 1;   // phase B: token half
    const int hgrp = tid >> 7;         // phase B: hidden half (reduced later)
    const float* cW1p = p.cW1 + (size_t)i*C*HC;
    const float* cW2p = p.cW2 + (size_t)i*HC*C;

    ull accB[20];
    #pragma unroll
    for (int q = 0; q < 20; q++) accB[q] = 0ull;

    for (int sc = 0; sc < 2; sc++) {
        // phase A: hact[t][h] = gelu(b1[h] + sum_c lnxT[c][t]*W1[c][h])
        {
            ull a0[10], a1[10];
            #pragma unroll
            for (int q = 0; q < 10; q++) { a0[q] = 0ull; a1[q] = 0ull; }
            const int h0 = sc*256 + htop;
            #pragma unroll 2
            for (int c = 0; c < 128; c++) {
                ull w0d = dup2(cW1p[c*HC + h0]);
                ull w1d = dup2(cW1p[c*HC + h0 + 128]);
                const ulonglong2* lr = (const ulonglong2*)&lnxT[c*LNP + thA*20];
                #pragma unroll
                for (int k = 0; k < 5; k++) {
                    ulonglong2 u = lr[k];
                    a0[2*k]   = fma2(u.x, w0d, a0[2*k]);
                    a0[2*k+1] = fma2(u.y, w0d, a0[2*k+1]);
                    a1[2*k]   = fma2(u.x, w1d, a1[2*k]);
                    a1[2*k+1] = fma2(u.y, w1d, a1[2*k+1]);
                }
            }
            const float b0 = cb1s[h0], b1 = cb1s[h0 + 128];
            #pragma unroll
            for (int q = 0; q < 10; q++) {
                float x, y;
                unpack2(a0[q], x, y);
                *(float2*)&hactT[htop*HACTP + thA*20 + 2*q] =
                    make_float2(gelu_f(x + b0), gelu_f(y + b0));
                unpack2(a1[q], x, y);
                *(float2*)&hactT[(htop+128)*HACTP + thA*20 + 2*q] =
                    make_float2(gelu_f(x + b1), gelu_f(y + b1));
            }
        }
        __syncthreads();
        // phase B: acc[t][c] += sum_h hactT[h][t]*W2[h][c]  (this thread: 128 h)
        {
            const float* w2base = cW2p + (size_t)(sc*256 + hgrp*128)*C;
            #pragma unroll 2
            for (int ii = 0; ii < 128; ii++) {
                ull w0d = dup2(w2base[ii*C + c0]);
                ull w1d = dup2(w2base[ii*C + c1]);
                const ulonglong2* hr =
                    (const ulonglong2*)&hactT[(hgrp*128 + ii)*HACTP + thB*20];
                #pragma unroll
                for (int k = 0; k < 5; k++) {
                    ulonglong2 u = hr[k];
                    accB[2*k]      = fma2(u.x, w0d, accB[2*k]);
                    accB[2*k+1]    = fma2(u.y, w0d, accB[2*k+1]);
                    accB[10+2*k]   = fma2(u.x, w1d, accB[10+2*k]);
                    accB[10+2*k+1] = fma2(u.y, w1d, accB[10+2*k+1]);
                }
            }
        }
        __syncthreads();
    }

    // ---- cross-hgrp reduction + writeback ----
    if (tid >= 128) {
        float* st = stage + (tid - 128)*STAGEP;
        #pragma unroll
        for (int q = 0; q < 20; q++) {
            float x, y; unpack2(accB[q], x, y);
            st[2*q] = x; st[2*q+1] = y;
        }
    }
    __syncthreads();
    if (tid < 128) {
        const float* st = stage + tid*STAGEP;   // partner tid+128 wrote here
        const float add0 = cb2s[c0], add1 = cb2s[c1];
        #pragma unroll
        for (int q = 0; q < 10; q++) {
            float x, y; unpack2(accB[q], x, y);
            const int t = thB*20 + 2*q;
            tok[t*TOKP + c0]     += x + st[2*q]   + add0;
            tok[(t+1)*TOKP + c0] += y + st[2*q+1] + add0;
        }
        #pragma unroll
        for (int q = 0; q < 10; q++) {
            float x, y; unpack2(accB[10+q], x, y);
            const int t = thB*20 + 2*q;
            tok[t*TOKP + c1]     += x + st[20+2*q]   + add1;
            tok[(t+1)*TOKP + c1] += y + st[20+2*q+1] + add1;
        }
    }
    __syncthreads();
}

__global__ __launch_bounds__(256, 2)
void repeat_mixer_kernel(P p) {
    const int b   = blockIdx.x;
    const int tid = threadIdx.x;
    extern __shared__ float sm[];
    float* tok  = sm + OFF_TOK;
    float* emb1 = sm + OFF_EMB1;
    float* feat = sm + OFF_UNION;

    __shared__ int   s_eid[3][K];
    __shared__ float s_dt[K];

    // ================= one-hop branch =================
    for (int half = 0; half < 2; half++) {
        const int*   eidp = half ? p.dst_eids : p.src_eids;
        const float* dtp  = half ? p.dt_dst   : p.dt_src;
        if (tid < K) { s_eid[0][tid] = eidp[b*K + tid]; s_dt[tid] = dtp[b*K + tid]; }
        __syncthreads();
        for (int idx = tid; idx < K*228; idx += 256) {
            int t = idx / 228, j = idx - t*228;
            int eid = s_eid[0][t];
            float v;
            if (j < D) v = p.edge_table[(long long)eid*D + j];
            else {
                int jt = j - D;
                v = (eid == 0) ? 0.f : cosf(s_dt[t]*p.time_w[jt] + p.time_b[jt]);
            }
            feat[t*PITCH1 + j] = v;
        }
        __syncthreads();
        project(p.proj_W, p.proj_b, feat, tok, 57, PITCH1, half, tid);
        __syncthreads();
    }

    run_mixer(0, p, sm, tid);
    run_mixer(1, p, sm, tid);

    if (tid < C) {
        float s = 0.f;
        #pragma unroll 8
        for (int t = 0; t < TK; t++) s += tok[t*TOKP + tid];
        emb1[tid] = s * (1.0f/TK);
    }
    __syncthreads();

    // ================= two-hop branch =================
    for (int half = 0; half < 2; half++) {
        const int*   e1p = half ? p.dst2_e1  : p.src2_e1;
        const int*   e2p = half ? p.dst2_e2  : p.src2_e2;
        const int*   e0p = half ? p.dst_eids : p.src_eids;
        const float* dtp = half ? p.dt2_dst  : p.dt2_src;
        if (tid < K) {
            s_eid[0][tid] = e1p[b*K + tid];
            s_eid[1][tid] = e2p[b*K + tid];
            s_eid[2][tid] = e0p[b*K + tid];
            s_dt[tid]     = dtp[b*K + tid];
        }
        __syncthreads();
        for (int idx = tid; idx < K*484; idx += 256) {
            int t = idx / 484, j = idx - t*484;
            float v;
            if (j < 3*D) {
                int eid = s_eid[j >> 7][t];
                v = p.edge_table[(long long)eid*D + (j & 127)];
            } else {
                int jt = j - 3*D;
                int e1 = s_eid[0][t];
                v = (e1 == 0) ? 0.f : cosf(s_dt[t]*p.time_w[jt] + p.time_b[jt]);
            }
            feat[t*PITCH2 + j] = v;
        }
        __syncthreads();
        project(p.eproj_W + (size_t)half*484*C, p.eproj_b + half*C,
                feat, tok, 121, PITCH2, half, tid);
        __syncthreads();
    }

    run_mixer(2, p, sm, tid);
    run_mixer(3, p, sm, tid);

    if (tid < C) {
        float s = 0.f;
        #pragma unroll 8
        for (int t = 0; t < TK; t++) s += tok[t*TOKP + tid];
        float e2v = s * (1.0f/TK);
        float a1 = p.pcc1[b], a2 = p.pcc2[b];
        float mx = fmaxf(a1, a2);
        float x1 = expf(a1 - mx), x2 = expf(a2 - mx);
        float w1 = x1 / (x1 + x2);
        p.out[b*C + tid] = w1*emb1[tid] + (1.0f - w1)*e2v;
    }
}

extern "C" void kernel_launch(void* const* d_in, const int* in_sizes, int n_in,
                              void* d_out, int out_size) {
    P p;
    p.edge_table = (const float*)d_in[0];
    p.src_eids   = (const int*)  d_in[1];
    p.dst_eids   = (const int*)  d_in[2];
    p.src2_e1    = (const int*)  d_in[3];
    p.src2_e2    = (const int*)  d_in[4];
    p.dst2_e1    = (const int*)  d_in[5];
    p.dst2_e2    = (const int*)  d_in[6];
    p.dt_src     = (const float*)d_in[7];
    p.dt_dst     = (const float*)d_in[8];
    p.dt2_src    = (const float*)d_in[9];
    p.dt2_dst    = (const float*)d_in[10];
    p.pcc1       = (const float*)d_in[11];
    p.pcc2       = (const float*)d_in[12];
    p.time_w     = (const float*)d_in[13];
    p.time_b     = (const float*)d_in[14];
    p.proj_W     = (const float*)d_in[15];
    p.proj_b     = (const float*)d_in[16];
    p.eproj_W    = (const float*)d_in[17];
    p.eproj_b    = (const float*)d_in[18];
    p.tln_g      = (const float*)d_in[19];
    p.tln_b      = (const float*)d_in[20];
    p.tW1        = (const float*)d_in[21];
    p.tb1        = (const float*)d_in[22];
    p.tW2        = (const float*)d_in[23];
    p.tb2        = (const float*)d_in[24];
    p.cln_g      = (const float*)d_in[25];
    p.cln_b      = (const float*)d_in[26];
    p.cW1        = (const float*)d_in[27];
    p.cb1        = (const float*)d_in[28];
    p.cW2        = (const float*)d_in[29];
    p.cb2        = (const float*)d_in[30];
    p.out        = (float*)d_out;

    const int smem_bytes = SMEM_FLOATS * (int)sizeof(float);
    cudaFuncSetAttribute(repeat_mixer_kernel,
                         cudaFuncAttributeMaxDynamicSharedMemorySize, smem_bytes);
    repeat_mixer_kernel<<<BATCH, 256, smem_bytes>>>(p);
}